// round 1
// baseline (speedup 1.0000x reference)
#include <cuda_runtime.h>

// ---------------- problem constants (fixed for this problem instance) -------
#define RR     128                  // spatial resolution of planes & features
#define CHP    48                   // plane channels = OUT_DIM*TIME_RANK*RANK
#define TT     150                  // time resolution
#define NFEAT  32                   // feature channels
#define R3     (128*128*128)
#define MAXN   (4096*128)

// smem weight layout offsets (floats)
#define OFF_W1   0        // [35][64]
#define OFF_B1   2240
#define OFF_W2   2304     // [64][16]
#define OFF_B2   3328
#define OFF_WC1  3344     // [18][64]
#define OFF_BC1  4496
#define OFF_WC2  4560     // [64][3]
#define OFF_BC2  4752
#define SW_TOT   4755

// ---------------- scratch (__device__ globals; no allocation allowed) -------
__device__ float  g_gsT[3 * RR * RR * CHP];   // channel-last planes: [c][y][x][48]
__device__ float4 g_pt[MAXN];                 // per-point {tau, r, g, b}

// ---------------- helpers ---------------------------------------------------
__device__ __forceinline__ float4 f4fma(float a, float4 b, float4 c) {
    c.x = fmaf(a, b.x, c.x); c.y = fmaf(a, b.y, c.y);
    c.z = fmaf(a, b.z, c.z); c.w = fmaf(a, b.w, c.w);
    return c;
}
__device__ __forceinline__ float4 f4mul(float4 a, float4 b) {
    return make_float4(a.x*b.x, a.y*b.y, a.z*b.z, a.w*b.w);
}
__device__ __forceinline__ float4 f4wsum(float w00, float4 a, float w01, float4 b,
                                         float w10, float4 c, float w11, float4 d) {
    float4 r;
    r.x = fmaf(w00,a.x, fmaf(w01,b.x, fmaf(w10,c.x, w11*d.x)));
    r.y = fmaf(w00,a.y, fmaf(w01,b.y, fmaf(w10,c.y, w11*d.y)));
    r.z = fmaf(w00,a.z, fmaf(w01,b.z, fmaf(w10,c.z, w11*d.z)));
    r.w = fmaf(w00,a.w, fmaf(w01,b.w, fmaf(w10,c.w, w11*d.w)));
    return r;
}

// ---------------- kernel 0: transpose grid_space to channel-last ------------
// in:  [3][48][128][128]   out: [c][y][x][48]
__global__ void transpose_gs(const float* __restrict__ gs) {
    int idx = blockIdx.x * blockDim.x + threadIdx.x;
    const int total = 3 * CHP * RR * RR;
    if (idx >= total) return;
    int x  = idx & (RR - 1);
    int y  = (idx >> 7) & (RR - 1);
    int t  = idx >> 14;          // c*48 + ch
    int ch = t % CHP;
    int c  = t / CHP;
    g_gsT[(((c * RR + y) * RR + x) * CHP) + ch] = gs[idx];
}

// ---------------- kernel 1: per-point pipeline ------------------------------
__global__ __launch_bounds__(128)
void point_kernel(const float* __restrict__ rays_d,
                  const float* __restrict__ pts,
                  const float* __restrict__ times,
                  const float* __restrict__ deltas,
                  const float* __restrict__ grid_time,
                  const float* __restrict__ features,
                  const float* __restrict__ W1,  const float* __restrict__ b1,
                  const float* __restrict__ W2,  const float* __restrict__ b2,
                  const float* __restrict__ Wc1, const float* __restrict__ bc1,
                  const float* __restrict__ Wc2, const float* __restrict__ bc2,
                  const int*   __restrict__ ridx,
                  int N)
{
    __shared__ float sw[SW_TOT];
    {
        int t = threadIdx.x;
        for (int k = t; k < 2240; k += 128) sw[OFF_W1  + k] = W1[k];
        for (int k = t; k < 64;   k += 128) sw[OFF_B1  + k] = b1[k];
        for (int k = t; k < 1024; k += 128) sw[OFF_W2  + k] = W2[k];
        for (int k = t; k < 16;   k += 128) sw[OFF_B2  + k] = b2[k];
        for (int k = t; k < 1152; k += 128) sw[OFF_WC1 + k] = Wc1[k];
        for (int k = t; k < 64;   k += 128) sw[OFF_BC1 + k] = bc1[k];
        for (int k = t; k < 192;  k += 128) sw[OFF_WC2 + k] = Wc2[k];
        for (int k = t; k < 3;    k += 128) sw[OFF_BC2 + k] = bc2[k];
    }
    __syncthreads();

    int i = blockIdx.x * 128 + threadIdx.x;
    if (i >= N) return;

    // ---- normalized ray dir ----
    int r = ridx[i];
    float dx = rays_d[r*3+0], dy = rays_d[r*3+1], dz = rays_d[r*3+2];
    float inv = rsqrtf(dx*dx + dy*dy + dz*dz);
    float rdx = dx*inv, rdy = dy*inv, rdz = dz*inv;

    // ---- per-dim bilinear setup for pts ----
    float p0 = pts[i*3+0], p1 = pts[i*3+1], p2 = pts[i*3+2];
    int   i0[3]; float wv[3];
    {
        float pv[3] = {p0, p1, p2};
        #pragma unroll
        for (int d = 0; d < 3; d++) {
            float x = (pv[d] + 1.0f) * 0.5f * (float)(RR - 1);
            x = fminf(fmaxf(x, 0.0f), (float)(RR - 1));
            int ii = (int)floorf(x);
            ii = min(ii, RR - 2);
            i0[d] = ii;
            wv[d] = x - (float)ii;
        }
    }

    // ---- tri-plane gather: prod over 3 planes of bilinear-sampled 48-vec ----
    float4 prod[12];
    const int comba[3] = {0, 0, 1};
    const int combb[3] = {1, 2, 2};
    #pragma unroll
    for (int c = 0; c < 3; c++) {
        int a = comba[c], b = combb[c];
        const float* cell = g_gsT + (((c * RR + i0[a]) * RR) + i0[b]) * CHP;
        const float4* g00 = (const float4*)cell;
        const float4* g01 = g00 + (CHP / 4);               // b+1
        const float4* g10 = (const float4*)(cell + RR * CHP); // a+1
        const float4* g11 = g10 + (CHP / 4);
        float wa = wv[a], wb = wv[b];
        float w00 = (1.0f-wa)*(1.0f-wb), w01 = (1.0f-wa)*wb;
        float w10 = wa*(1.0f-wb),        w11 = wa*wb;
        #pragma unroll
        for (int k = 0; k < 12; k++) {
            float4 v = f4wsum(w00, __ldg(g00+k), w01, __ldg(g01+k),
                              w10, __ldg(g10+k), w11, __ldg(g11+k));
            prod[k] = (c == 0) ? v : f4mul(prod[k], v);
        }
    }

    // ---- time interpolation + contraction -> coords[3] ----
    float tv = times[i];
    float xt = (tv + 1.0f) * 0.5f * (float)(TT - 1);
    xt = fminf(fmaxf(xt, 0.0f), (float)(TT - 1));
    int   it0 = min((int)floorf(xt), TT - 2);
    float wt  = xt - (float)it0;

    float coords[3];
    #pragma unroll
    for (int o = 0; o < 3; o++) {
        float acc = 0.0f;
        #pragma unroll
        for (int tq = 0; tq < 4; tq++) {
            int j = o*4 + tq;   // chunk j = ranks of (o, tq)
            float M = prod[j].x + prod[j].y + prod[j].z + prod[j].w;
            float itv = __ldg(&grid_time[j*TT + it0])     * (1.0f - wt)
                      + __ldg(&grid_time[j*TT + it0 + 1]) * wt;
            acc = fmaf(M, itv, acc);
        }
        coords[o] = fminf(fmaxf(acc, -1.0f), 1.0f);
    }

    // ---- feature grid trilinear setup ----
    int   f0[3]; float fw[3];
    #pragma unroll
    for (int d = 0; d < 3; d++) {
        float x = (coords[d] + 1.0f) * 0.5f * (float)(RR - 1);
        x = fminf(fmaxf(x, 0.0f), (float)(RR - 1));
        int ii = (int)floorf(x);
        ii = min(ii, RR - 2);
        f0[d] = ii;
        fw[d] = x - (float)ii;
    }
    int   coff[8]; float cw[8];
    #pragma unroll
    for (int corner = 0; corner < 8; corner++) {
        int b0 = corner & 1, b1_ = (corner >> 1) & 1, b2_ = (corner >> 2) & 1;
        int o0 = f0[0] + b0, o1 = f0[1] + b1_, o2 = f0[2] + b2_;
        coff[corner] = (o0 * RR + o1) * RR + o2;
        cw[corner] = (b0 ? fw[0] : 1.0f - fw[0])
                   * (b1_ ? fw[1] : 1.0f - fw[1])
                   * (b2_ ? fw[2] : 1.0f - fw[2]);
    }

    // ---- MLP1: [feats(32), rd(3)] @ W1 + b1, fused with feature gather ----
    float4 h4[16];
    {
        const float4* bb = (const float4*)(sw + OFF_B1);
        #pragma unroll
        for (int k = 0; k < 16; k++) h4[k] = bb[k];
    }
    for (int ch = 0; ch < NFEAT; ch++) {           // dynamic loop: ptr arith only
        const float* fb = features + (size_t)ch * R3;
        float v = 0.0f;
        #pragma unroll
        for (int corner = 0; corner < 8; corner++)
            v = fmaf(cw[corner], __ldg(fb + coff[corner]), v);
        const float4* wrow = (const float4*)(sw + OFF_W1 + ch * 64);
        #pragma unroll
        for (int k = 0; k < 16; k++) h4[k] = f4fma(v, wrow[k], h4[k]);
    }
    {
        float rdv[3] = {rdx, rdy, rdz};
        #pragma unroll
        for (int j = 0; j < 3; j++) {
            const float4* wrow = (const float4*)(sw + OFF_W1 + (32 + j) * 64);
            float v = rdv[j];
            #pragma unroll
            for (int k = 0; k < 16; k++) h4[k] = f4fma(v, wrow[k], h4[k]);
        }
    }

    // ---- stage 2: relu(h) @ W2 + b2 -> s[16] ----
    float4 s40, s41, s42, s43;
    {
        const float4* bb = (const float4*)(sw + OFF_B2);
        s40 = bb[0]; s41 = bb[1]; s42 = bb[2]; s43 = bb[3];
    }
    #pragma unroll
    for (int k4 = 0; k4 < 16; k4++) {
        float hv[4] = {h4[k4].x, h4[k4].y, h4[k4].z, h4[k4].w};
        #pragma unroll
        for (int cc = 0; cc < 4; cc++) {
            float hj = fmaxf(hv[cc], 0.0f);
            const float4* w2r = (const float4*)(sw + OFF_W2 + (k4*4 + cc) * 16);
            s40 = f4fma(hj, w2r[0], s40);
            s41 = f4fma(hj, w2r[1], s41);
            s42 = f4fma(hj, w2r[2], s42);
            s43 = f4fma(hj, w2r[3], s43);
        }
    }

    float sigma = expf(fminf(fmaxf(s40.x, -15.0f), 15.0f));

    // ---- MLP2: [geo(15), rd(3)] @ Wc1 + bc1 -> relu -> @ Wc2 + bc2 ----
    float gin[18] = {
        s40.y, s40.z, s40.w,
        s41.x, s41.y, s41.z, s41.w,
        s42.x, s42.y, s42.z, s42.w,
        s43.x, s43.y, s43.z, s43.w,
        rdx, rdy, rdz
    };
    float4 hc4[16];
    {
        const float4* bb = (const float4*)(sw + OFF_BC1);
        #pragma unroll
        for (int k = 0; k < 16; k++) hc4[k] = bb[k];
    }
    #pragma unroll
    for (int j = 0; j < 18; j++) {
        const float4* wrow = (const float4*)(sw + OFF_WC1 + j * 64);
        float v = gin[j];
        #pragma unroll
        for (int k = 0; k < 16; k++) hc4[k] = f4fma(v, wrow[k], hc4[k]);
    }
    float cr = sw[OFF_BC2+0], cg = sw[OFF_BC2+1], cb = sw[OFF_BC2+2];
    #pragma unroll
    for (int k4 = 0; k4 < 16; k4++) {
        float hv[4] = {hc4[k4].x, hc4[k4].y, hc4[k4].z, hc4[k4].w};
        #pragma unroll
        for (int cc = 0; cc < 4; cc++) {
            float hj = fmaxf(hv[cc], 0.0f);
            int j = k4*4 + cc;
            cr = fmaf(hj, sw[OFF_WC2 + j*3 + 0], cr);
            cg = fmaf(hj, sw[OFF_WC2 + j*3 + 1], cg);
            cb = fmaf(hj, sw[OFF_WC2 + j*3 + 2], cb);
        }
    }
    cr = 1.0f / (1.0f + expf(-cr));
    cg = 1.0f / (1.0f + expf(-cg));
    cb = 1.0f / (1.0f + expf(-cb));

    float tau = sigma * deltas[i];
    g_pt[i] = make_float4(tau, cr, cg, cb);
}

// ---------------- kernel 2: per-ray volume rendering ------------------------
// One block of S(=128) threads per ray. Exclusive scan of tau + weighted sums.
__global__ __launch_bounds__(128)
void ray_kernel(const float* __restrict__ bg_color,
                float* __restrict__ out, int S)
{
    int r = blockIdx.x;
    int t = threadIdx.x;
    float4 v = g_pt[r * S + t];
    float tau = v.x;

    // inclusive warp scan
    float x = tau;
    #pragma unroll
    for (int off = 1; off < 32; off <<= 1) {
        float y = __shfl_up_sync(0xffffffffu, x, off);
        if ((t & 31) >= off) x += y;
    }
    __shared__ float wsum[4];
    int lane = t & 31, wid = t >> 5;
    if (lane == 31) wsum[wid] = x;
    __syncthreads();
    float pre = 0.0f;
    #pragma unroll
    for (int w = 0; w < 4; w++) if (w < wid) pre += wsum[w];
    float incl = x + pre;
    float excl = incl - tau;

    float Tr = expf(-excl);
    float w  = Tr * (1.0f - expf(-tau));
    float sr = w * v.y, sg = w * v.z, sb = w * v.w;

    // block reduce (w, sr, sg, sb)
    #pragma unroll
    for (int off = 16; off >= 1; off >>= 1) {
        w  += __shfl_down_sync(0xffffffffu, w,  off);
        sr += __shfl_down_sync(0xffffffffu, sr, off);
        sg += __shfl_down_sync(0xffffffffu, sg, off);
        sb += __shfl_down_sync(0xffffffffu, sb, off);
    }
    __shared__ float4 part[4];
    if (lane == 0) part[wid] = make_float4(w, sr, sg, sb);
    __syncthreads();
    if (t == 0) {
        float aw = 0, ar = 0, ag = 0, ab = 0;
        #pragma unroll
        for (int k = 0; k < 4; k++) {
            aw += part[k].x; ar += part[k].y; ag += part[k].z; ab += part[k].w;
        }
        float one_m = 1.0f - aw;
        out[r*3+0] = ar + one_m * bg_color[r*3+0];
        out[r*3+1] = ag + one_m * bg_color[r*3+1];
        out[r*3+2] = ab + one_m * bg_color[r*3+2];
    }
}

// ---------------- launch -----------------------------------------------------
extern "C" void kernel_launch(void* const* d_in, const int* in_sizes, int n_in,
                              void* d_out, int out_size)
{
    const float* rays_d  = (const float*)d_in[0];
    const float* pts     = (const float*)d_in[1];
    const float* times   = (const float*)d_in[2];
    const float* deltas  = (const float*)d_in[3];
    const float* bg      = (const float*)d_in[4];
    const float* gs      = (const float*)d_in[5];
    const float* gt      = (const float*)d_in[6];
    const float* feats   = (const float*)d_in[7];
    const float* W1      = (const float*)d_in[8];
    const float* b1      = (const float*)d_in[9];
    const float* W2      = (const float*)d_in[10];
    const float* b2      = (const float*)d_in[11];
    const float* Wc1     = (const float*)d_in[12];
    const float* bc1     = (const float*)d_in[13];
    const float* Wc2     = (const float*)d_in[14];
    const float* bc2     = (const float*)d_in[15];
    const int*   ridx    = (const int*)d_in[16];
    // d_in[17] = boundary (implied by contiguous per-ray segments; unused)

    int n_rays = in_sizes[0] / 3;
    int N      = in_sizes[2];
    int S      = N / n_rays;
    float* out = (float*)d_out;

    {
        const int total = 3 * CHP * RR * RR;
        transpose_gs<<<(total + 255) / 256, 256>>>(gs);
    }
    point_kernel<<<(N + 127) / 128, 128>>>(rays_d, pts, times, deltas, gt, feats,
                                           W1, b1, W2, b2, Wc1, bc1, Wc2, bc2,
                                           ridx, N);
    ray_kernel<<<n_rays, S>>>(bg, out, S);
}

// round 4
// speedup vs baseline: 1.5674x; 1.5674x over previous
#include <cuda_runtime.h>
#include <cuda_bf16.h>

// ---------------- problem constants -----------------------------------------
#define RR     128
#define CHP    48                  // plane channels = OUT_DIM*TIME_RANK*RANK
#define TT     150
#define NFEAT  32
#define R3     (128*128*128)
#define MAXN   (4096*128)

// smem weight layout offsets (floats)
#define OFF_W1   0        // [35][64]
#define OFF_B1   2240
#define OFF_W2   2304     // [64][16]
#define OFF_B2   3328
#define OFF_WC1  3344     // [18][64]
#define OFF_BC1  4496
#define OFF_WC2  4560     // [64][3]
#define OFF_BC2  4752
#define SW_TOT   4756

typedef unsigned long long u64;

// ---------------- scratch (__device__ globals) -------------------------------
__device__ __nv_bfloat16 g_gsTb[3 * RR * RR * CHP];  // bf16 channel-last planes
__device__ float         g_gtT[TT * 12];             // time grid, [t][12]
__device__ float4        g_coords[MAXN];
__device__ float4        g_pt[MAXN];                 // {tau, r, g, b}

// ---------------- packed fp32x2 helpers (sm_103a FFMA2) ----------------------
__device__ __forceinline__ u64 ffma2(u64 a, u64 b, u64 c) {
    u64 d; asm("fma.rn.f32x2 %0,%1,%2,%3;" : "=l"(d) : "l"(a), "l"(b), "l"(c));
    return d;
}
__device__ __forceinline__ u64 pack2(float x) {
    u64 d; asm("mov.b64 %0,{%1,%1};" : "=l"(d) : "f"(x)); return d;
}
__device__ __forceinline__ float2 unpack2(u64 a) {
    float2 r; asm("mov.b64 {%0,%1},%2;" : "=f"(r.x), "=f"(r.y) : "l"(a)); return r;
}
__device__ __forceinline__ __nv_bfloat162 bf2u(unsigned u) {
    __nv_bfloat162 r; *reinterpret_cast<unsigned*>(&r) = u; return r;
}

// ---------------- kernel 0: prep (plane transpose->bf16, time transpose) -----
// grid = 3*128 + 1 blocks of 256 threads
__global__ void prep_kernel(const float* __restrict__ gs,
                            const float* __restrict__ gt) {
    int b = blockIdx.x;
    if (b < 3 * RR) {
        __shared__ __nv_bfloat16 tile[RR * 50];
        int c = b >> 7, y = b & 127;
        const float* src = gs + (size_t)(c * CHP) * (RR * RR) + y * RR;
        for (int t = threadIdx.x; t < CHP * RR; t += 256) {
            int ch = t >> 7, x = t & 127;
            tile[x * 50 + ch] = __float2bfloat16(src[ch * (RR * RR) + x]);
        }
        __syncthreads();
        __nv_bfloat162* dst =
            (__nv_bfloat162*)(g_gsTb + (size_t)(c * RR + y) * (RR * CHP));
        for (int t = threadIdx.x; t < RR * (CHP / 2); t += 256) {
            int x = t / (CHP / 2), ch = (t - x * (CHP / 2)) * 2;
            __nv_bfloat162 v;
            v.x = tile[x * 50 + ch];
            v.y = tile[x * 50 + ch + 1];
            dst[t] = v;
        }
    } else {
        for (int t = threadIdx.x; t < 12 * TT; t += 256) {
            int j = t / TT, tt = t - j * TT;
            g_gtT[tt * 12 + j] = gt[t];
        }
    }
}

// ---------------- kernel 1: coords (plane gather + time contraction) ---------
__global__ __launch_bounds__(128)
void coord_kernel(const float* __restrict__ pts,
                  const float* __restrict__ times, int N) {
    int i = blockIdx.x * 128 + threadIdx.x;
    if (i >= N) return;

    int i0[3]; float wv[3];
    #pragma unroll
    for (int d = 0; d < 3; d++) {
        float x = (pts[i * 3 + d] + 1.0f) * 0.5f * (float)(RR - 1);
        x = fminf(fmaxf(x, 0.0f), (float)(RR - 1));
        int ii = min((int)floorf(x), RR - 2);
        i0[d] = ii; wv[d] = x - (float)ii;
    }

    __nv_bfloat162 prod[24];
    const int comba[3] = {0, 0, 1};
    const int combb[3] = {1, 2, 2};
    #pragma unroll
    for (int c = 0; c < 3; c++) {
        int a = comba[c], bb_ = combb[c];
        const __nv_bfloat16* cell =
            g_gsTb + (size_t)((c * RR + i0[a]) * RR + i0[bb_]) * CHP;
        const uint4* r0 = (const uint4*)cell;              // corner00 (6 uint4), corner01 at +6
        const uint4* r1 = (const uint4*)(cell + RR * CHP); // corner10, corner11
        float wa = wv[a], wb = wv[bb_];
        __nv_bfloat162 w00 = __float2bfloat162_rn((1.0f - wa) * (1.0f - wb));
        __nv_bfloat162 w01 = __float2bfloat162_rn((1.0f - wa) * wb);
        __nv_bfloat162 w10 = __float2bfloat162_rn(wa * (1.0f - wb));
        __nv_bfloat162 w11 = __float2bfloat162_rn(wa * wb);
        #pragma unroll
        for (int kc = 0; kc < 6; kc++) {
            uint4 q00 = __ldg(r0 + kc);
            uint4 q01 = __ldg(r0 + 6 + kc);
            uint4 q10 = __ldg(r1 + kc);
            uint4 q11 = __ldg(r1 + 6 + kc);
            const unsigned* e00 = &q00.x;
            const unsigned* e01 = &q01.x;
            const unsigned* e10 = &q10.x;
            const unsigned* e11 = &q11.x;
            #pragma unroll
            for (int u = 0; u < 4; u++) {
                __nv_bfloat162 v = __hmul2(bf2u(e00[u]), w00);
                v = __hfma2(bf2u(e01[u]), w01, v);
                v = __hfma2(bf2u(e10[u]), w10, v);
                v = __hfma2(bf2u(e11[u]), w11, v);
                int k = kc * 4 + u;
                prod[k] = (c == 0) ? v : __hmul2(prod[k], v);
            }
        }
    }

    // time interpolation: contiguous [it0][12],[it0+1][12]
    float tv = times[i];
    float xt = (tv + 1.0f) * 0.5f * (float)(TT - 1);
    xt = fminf(fmaxf(xt, 0.0f), (float)(TT - 1));
    int it0 = min((int)floorf(xt), TT - 2);
    float wt = xt - (float)it0;
    const float4* tp = (const float4*)(g_gtT + it0 * 12);
    float tr[24];
    *(float4*)(tr +  0) = __ldg(tp + 0);
    *(float4*)(tr +  4) = __ldg(tp + 1);
    *(float4*)(tr +  8) = __ldg(tp + 2);
    *(float4*)(tr + 12) = __ldg(tp + 3);
    *(float4*)(tr + 16) = __ldg(tp + 4);
    *(float4*)(tr + 20) = __ldg(tp + 5);

    float co[3];
    #pragma unroll
    for (int o = 0; o < 3; o++) {
        float acc = 0.0f;
        #pragma unroll
        for (int tq = 0; tq < 4; tq++) {
            int j = o * 4 + tq;
            float2 x0 = __bfloat1622float2(prod[2 * j]);
            float2 x1 = __bfloat1622float2(prod[2 * j + 1]);
            float M = (x0.x + x0.y) + (x1.x + x1.y);
            float itv = tr[j] + wt * (tr[12 + j] - tr[j]);
            acc = fmaf(M, itv, acc);
        }
        co[o] = fminf(fmaxf(acc, -1.0f), 1.0f);
    }
    g_coords[i] = make_float4(co[0], co[1], co[2], 0.0f);
}

// ---------------- kernel 2: feature gather + MLPs (packed fp32x2) ------------
#define PPT 4
__global__ __launch_bounds__(128)
void mlp_kernel(const float* __restrict__ rays_d,
                const float* __restrict__ deltas,
                const float* __restrict__ features,
                const float* __restrict__ W1,  const float* __restrict__ b1,
                const float* __restrict__ W2,  const float* __restrict__ b2,
                const float* __restrict__ Wc1, const float* __restrict__ bc1,
                const float* __restrict__ Wc2, const float* __restrict__ bc2,
                const int*   __restrict__ ridx, int N)
{
    __shared__ __align__(16) float sw[SW_TOT];
    {
        int t = threadIdx.x;
        for (int k = t; k < 2240; k += 128) sw[OFF_W1  + k] = W1[k];
        for (int k = t; k < 64;   k += 128) sw[OFF_B1  + k] = b1[k];
        for (int k = t; k < 1024; k += 128) sw[OFF_W2  + k] = W2[k];
        for (int k = t; k < 16;   k += 128) sw[OFF_B2  + k] = b2[k];
        for (int k = t; k < 1152; k += 128) sw[OFF_WC1 + k] = Wc1[k];
        for (int k = t; k < 64;   k += 128) sw[OFF_BC1 + k] = bc1[k];
        for (int k = t; k < 192;  k += 128) sw[OFF_WC2 + k] = Wc2[k];
        for (int k = t; k < 3;    k += 128) sw[OFF_BC2 + k] = bc2[k];
    }
    __syncthreads();

    int base = blockIdx.x * (128 * PPT) + threadIdx.x;
    #pragma unroll 1
    for (int itp = 0; itp < PPT; itp++) {
        int i = base + itp * 128;
        if (i >= N) break;

        int r = ridx[i];
        float dx = rays_d[r*3+0], dy = rays_d[r*3+1], dz = rays_d[r*3+2];
        float inv = rsqrtf(dx*dx + dy*dy + dz*dz);
        float rdx = dx*inv, rdy = dy*inv, rdz = dz*inv;

        float4 cvv = g_coords[i];
        float co[3] = {cvv.x, cvv.y, cvv.z};
        int f0[3]; float fw[3];
        #pragma unroll
        for (int d = 0; d < 3; d++) {
            float x = (co[d] + 1.0f) * 0.5f * (float)(RR - 1);
            x = fminf(fmaxf(x, 0.0f), (float)(RR - 1));
            int ii = min((int)floorf(x), RR - 2);
            f0[d] = ii; fw[d] = x - (float)ii;
        }
        int coff[8]; float cwv[8];
        #pragma unroll
        for (int corner = 0; corner < 8; corner++) {
            int b0 = corner & 1, b1_ = (corner >> 1) & 1, b2_ = (corner >> 2) & 1;
            coff[corner] = ((f0[0]+b0) * RR + (f0[1]+b1_)) * RR + (f0[2]+b2_);
            cwv[corner] = (b0 ? fw[0] : 1.0f - fw[0])
                        * (b1_ ? fw[1] : 1.0f - fw[1])
                        * (b2_ ? fw[2] : 1.0f - fw[2]);
        }

        // ---- MLP1 (packed): bias + rd rows + fused feature gather ----
        u64 hA[32];
        {
            const ulonglong2* bb = (const ulonglong2*)(sw + OFF_B1);
            #pragma unroll
            for (int k = 0; k < 16; k++) { ulonglong2 t = bb[k]; hA[2*k] = t.x; hA[2*k+1] = t.y; }
        }
        {
            float rv[3] = {rdx, rdy, rdz};
            #pragma unroll
            for (int j = 0; j < 3; j++) {
                u64 vv = pack2(rv[j]);
                const ulonglong2* wr = (const ulonglong2*)(sw + OFF_W1 + (32 + j) * 64);
                #pragma unroll
                for (int k = 0; k < 16; k++) {
                    ulonglong2 w = wr[k];
                    hA[2*k]   = ffma2(vv, w.x, hA[2*k]);
                    hA[2*k+1] = ffma2(vv, w.y, hA[2*k+1]);
                }
            }
        }
        #pragma unroll 4
        for (int ch = 0; ch < NFEAT; ch++) {
            const float* fb = features + (size_t)ch * R3;
            float v = 0.0f;
            #pragma unroll
            for (int k = 0; k < 8; k++) v = fmaf(cwv[k], __ldg(fb + coff[k]), v);
            u64 vv = pack2(v);
            const ulonglong2* wr = (const ulonglong2*)(sw + OFF_W1 + ch * 64);
            #pragma unroll
            for (int k = 0; k < 16; k++) {
                ulonglong2 w = wr[k];
                hA[2*k]   = ffma2(vv, w.x, hA[2*k]);
                hA[2*k+1] = ffma2(vv, w.y, hA[2*k+1]);
            }
        }

        // ---- stage 2: relu(h) @ W2 + b2 ----
        u64 sA[8];
        {
            const ulonglong2* bb = (const ulonglong2*)(sw + OFF_B2);
            #pragma unroll
            for (int j = 0; j < 4; j++) { ulonglong2 t = bb[j]; sA[2*j] = t.x; sA[2*j+1] = t.y; }
        }
        #pragma unroll
        for (int k = 0; k < 32; k++) {
            float2 h2 = unpack2(hA[k]);
            float h0 = fmaxf(h2.x, 0.0f), h1 = fmaxf(h2.y, 0.0f);
            {
                u64 vv = pack2(h0);
                const ulonglong2* wr = (const ulonglong2*)(sw + OFF_W2 + (2*k) * 16);
                #pragma unroll
                for (int j = 0; j < 4; j++) {
                    ulonglong2 w = wr[j];
                    sA[2*j]   = ffma2(vv, w.x, sA[2*j]);
                    sA[2*j+1] = ffma2(vv, w.y, sA[2*j+1]);
                }
            }
            {
                u64 vv = pack2(h1);
                const ulonglong2* wr = (const ulonglong2*)(sw + OFF_W2 + (2*k+1) * 16);
                #pragma unroll
                for (int j = 0; j < 4; j++) {
                    ulonglong2 w = wr[j];
                    sA[2*j]   = ffma2(vv, w.x, sA[2*j]);
                    sA[2*j+1] = ffma2(vv, w.y, sA[2*j+1]);
                }
            }
        }
        float s[16];
        #pragma unroll
        for (int j = 0; j < 8; j++) {
            float2 t = unpack2(sA[j]); s[2*j] = t.x; s[2*j+1] = t.y;
        }

        float sigma = __expf(fminf(fmaxf(s[0], -15.0f), 15.0f));

        // ---- MLP2 (color) ----
        float gin[18];
        #pragma unroll
        for (int j = 0; j < 15; j++) gin[j] = s[j + 1];
        gin[15] = rdx; gin[16] = rdy; gin[17] = rdz;

        u64 cA[32];
        {
            const ulonglong2* bb = (const ulonglong2*)(sw + OFF_BC1);
            #pragma unroll
            for (int k = 0; k < 16; k++) { ulonglong2 t = bb[k]; cA[2*k] = t.x; cA[2*k+1] = t.y; }
        }
        #pragma unroll
        for (int j = 0; j < 18; j++) {
            u64 vv = pack2(gin[j]);
            const ulonglong2* wr = (const ulonglong2*)(sw + OFF_WC1 + j * 64);
            #pragma unroll
            for (int k = 0; k < 16; k++) {
                ulonglong2 w = wr[k];
                cA[2*k]   = ffma2(vv, w.x, cA[2*k]);
                cA[2*k+1] = ffma2(vv, w.y, cA[2*k+1]);
            }
        }
        float cr = sw[OFF_BC2+0], cg = sw[OFF_BC2+1], cb = sw[OFF_BC2+2];
        #pragma unroll
        for (int k = 0; k < 32; k++) {
            float2 h2 = unpack2(cA[k]);
            float h0 = fmaxf(h2.x, 0.0f), h1 = fmaxf(h2.y, 0.0f);
            const float* w0 = sw + OFF_WC2 + (2*k) * 3;
            cr = fmaf(h0, w0[0], cr); cg = fmaf(h0, w0[1], cg); cb = fmaf(h0, w0[2], cb);
            cr = fmaf(h1, w0[3], cr); cg = fmaf(h1, w0[4], cg); cb = fmaf(h1, w0[5], cb);
        }
        cr = 1.0f / (1.0f + __expf(-cr));
        cg = 1.0f / (1.0f + __expf(-cg));
        cb = 1.0f / (1.0f + __expf(-cb));

        float tau = sigma * deltas[i];
        g_pt[i] = make_float4(tau, cr, cg, cb);
    }
}

// ---------------- kernel 3: per-ray volume rendering -------------------------
__global__ __launch_bounds__(128)
void ray_kernel(const float* __restrict__ bg_color,
                float* __restrict__ out, int S)
{
    int r = blockIdx.x;
    int t = threadIdx.x;
    float4 v = g_pt[r * S + t];
    float tau = v.x;

    float x = tau;
    #pragma unroll
    for (int off = 1; off < 32; off <<= 1) {
        float y = __shfl_up_sync(0xffffffffu, x, off);
        if ((t & 31) >= off) x += y;
    }
    __shared__ float wsum[4];
    int lane = t & 31, wid = t >> 5;
    if (lane == 31) wsum[wid] = x;
    __syncthreads();
    float pre = 0.0f;
    #pragma unroll
    for (int w = 0; w < 4; w++) if (w < wid) pre += wsum[w];
    float excl = x + pre - tau;

    float Tr = __expf(-excl);
    float w  = Tr * (1.0f - __expf(-tau));
    float sr = w * v.y, sg = w * v.z, sb = w * v.w;

    #pragma unroll
    for (int off = 16; off >= 1; off >>= 1) {
        w  += __shfl_down_sync(0xffffffffu, w,  off);
        sr += __shfl_down_sync(0xffffffffu, sr, off);
        sg += __shfl_down_sync(0xffffffffu, sg, off);
        sb += __shfl_down_sync(0xffffffffu, sb, off);
    }
    __shared__ float4 part[4];
    if (lane == 0) part[wid] = make_float4(w, sr, sg, sb);
    __syncthreads();
    if (t == 0) {
        float aw = 0, ar = 0, ag = 0, ab = 0;
        #pragma unroll
        for (int k = 0; k < 4; k++) {
            aw += part[k].x; ar += part[k].y; ag += part[k].z; ab += part[k].w;
        }
        float one_m = 1.0f - aw;
        out[r*3+0] = ar + one_m * bg_color[r*3+0];
        out[r*3+1] = ag + one_m * bg_color[r*3+1];
        out[r*3+2] = ab + one_m * bg_color[r*3+2];
    }
}

// ---------------- launch ------------------------------------------------------
extern "C" void kernel_launch(void* const* d_in, const int* in_sizes, int n_in,
                              void* d_out, int out_size)
{
    const float* rays_d  = (const float*)d_in[0];
    const float* pts     = (const float*)d_in[1];
    const float* times   = (const float*)d_in[2];
    const float* deltas  = (const float*)d_in[3];
    const float* bg      = (const float*)d_in[4];
    const float* gs      = (const float*)d_in[5];
    const float* gt      = (const float*)d_in[6];
    const float* feats   = (const float*)d_in[7];
    const float* W1      = (const float*)d_in[8];
    const float* b1      = (const float*)d_in[9];
    const float* W2      = (const float*)d_in[10];
    const float* b2      = (const float*)d_in[11];
    const float* Wc1     = (const float*)d_in[12];
    const float* bc1     = (const float*)d_in[13];
    const float* Wc2     = (const float*)d_in[14];
    const float* bc2     = (const float*)d_in[15];
    const int*   ridx    = (const int*)d_in[16];

    int n_rays = in_sizes[0] / 3;
    int N      = in_sizes[2];
    int S      = N / n_rays;
    float* out = (float*)d_out;

    prep_kernel<<<3 * RR + 1, 256>>>(gs, gt);
    coord_kernel<<<(N + 127) / 128, 128>>>(pts, times, N);
    mlp_kernel<<<(N + 128 * PPT - 1) / (128 * PPT), 128>>>(
        rays_d, deltas, feats, W1, b1, W2, b2, Wc1, bc1, Wc2, bc2, ridx, N);
    ray_kernel<<<n_rays, S>>>(bg, out, S);
}